// round 10
// baseline (speedup 1.0000x reference)
#include <cuda_runtime.h>
#include <math.h>
#include <stdint.h>

#define D_IN   768
#define TWO_D  1536
#define Q_N    128
#define S_N    512
#define C_N    64
#define JCHUNKS 8
#define JPER   (TWO_D / JCHUNKS)    /* 192 */
#define KSPLIT 384
#define NTILES (24 * 10)            /* gemm output tiles (x,y) */

typedef unsigned long long ull;

// Scratch (device globals: allocation-free per harness rules)
__device__ float    v10_hq[Q_N * TWO_D];             // hq (+b1)  [128,1536]
__device__ float    v10_hs[S_N * TWO_D];             // hs        [512,1536]
__device__ float    v10_p0[NTILES * 64 * 64];        // split-K z=0 partial tiles
__device__ float    v10_p1[NTILES * 64 * 64];        // split-K z=1 partial tiles
__device__ unsigned v10_cnt[NTILES];                 // per-tile pair tickets
__device__ double   v10_part[JCHUNKS * Q_N * S_N];   // fp64 partial scores per j-chunk
__device__ double   v10_loss[Q_N];
__device__ unsigned v10_ticket = 0;

// fp32 -> tf32 RNA rounding (matches cuBLAS TF32 input quantization = reference)
__device__ __forceinline__ float v10_tf32(float x) {
    unsigned u;
    asm("cvt.rna.tf32.f32 %0, %1;" : "=r"(u) : "f"(x));
    return __uint_as_float(u);
}

// m16n8k8 tf32 mma (base ISA, sm_80+)
__device__ __forceinline__ void v10_mma(float d[4], const unsigned a[4], const unsigned b[2]) {
    asm volatile(
        "mma.sync.aligned.m16n8k8.row.col.f32.tf32.tf32.f32 "
        "{%0,%1,%2,%3}, {%4,%5,%6,%7}, {%8,%9}, {%0,%1,%2,%3};"
        : "+f"(d[0]), "+f"(d[1]), "+f"(d[2]), "+f"(d[3])
        : "r"(a[0]), "r"(a[1]), "r"(a[2]), "r"(a[3]), "r"(b[0]), "r"(b[1]));
}

// packed f32x2 (base ISA on sm_100+ family; SASS FADD2/FFMA2)
#define V10_ADD2(d, a, b) \
    asm("add.rn.f32x2 %0, %1, %2;" : "=l"(d) : "l"(a), "l"(b))
#define V10_FMA2(acc, t, w) \
    asm("fma.rn.f32x2 %0, %1, %2, %0;" : "+l"(acc) : "l"(t), "l"(w))

// packed relu on the ALU pipe (IMAX): valid for all non-NaN floats
__device__ __forceinline__ ull v10_relu2(ull t) {
    unsigned lo, hi;
    asm("mov.b64 {%0,%1}, %2;" : "=r"(lo), "=r"(hi) : "l"(t));
    int l2 = max((int)lo, 0);
    int h2 = max((int)hi, 0);
    ull r;
    asm("mov.b64 %0, {%1,%2};" : "=l"(r) : "r"((unsigned)l2), "r"((unsigned)h2));
    return r;
}

// ---------------------------------------------------------------------------
// TF32 tensor-core GEMM, split-K x2 with in-kernel deterministic pair reduce.
// CTA 64m x 64n x K384; 128 threads = 4 warps (2M x 2N), warp tile 32x32.
// 12 double-buffered k-tiles of 32, one barrier/iter.
// grid = (24, 10, 2) = 480 CTAs, occupancy 4 -> fully resident single wave.
// Each CTA writes its partial tile to scratch; second of the (z0,z1) pair
// sums both (fp add commutative -> bitwise deterministic) + bias -> h.
// ---------------------------------------------------------------------------
#define V10_ST     40
#define V10_ASZ    (2 * 64 * V10_ST)
#define V10_BSZ    (2 * 64 * V10_ST)
#define V10_SMEM   ((V10_ASZ + V10_BSZ) * 4)     /* 40960 B */

__global__ void __launch_bounds__(128, 4)
v10_gemm(const float* __restrict__ query,
         const float* __restrict__ support,
         const float* __restrict__ W1,
         const float* __restrict__ b1)
{
    extern __shared__ __align__(16) float smem[];
    float* As = smem;               // [2][64][40]
    float* Bs = smem + V10_ASZ;     // [2][64][40]
    __shared__ int sSecond;

    const int tid  = threadIdx.x;
    const int lane = tid & 31;
    const int wid  = tid >> 5;
    const int warpM = wid & 1;          // 0..1
    const int warpN = wid >> 1;         // 0..1
    const int g = lane >> 2;            // 0..7
    const int t = lane & 3;             // 0..3

    const int  z    = blockIdx.z;
    const int  kOff = z * KSPLIT;
    const bool isQ  = (blockIdx.y < 2);
    const int  tileIdx = blockIdx.y * 24 + blockIdx.x;
    const float* Arow = isQ ? (query + (size_t)blockIdx.y * 64 * D_IN)
                            : (support + (size_t)(blockIdx.y - 2) * 64 * D_IN);
    const int   wOff  = (isQ ? 0 : D_IN) + kOff;
    const int   jBase = blockIdx.x * 64;
    float* Crow = isQ ? (v10_hq + (size_t)blockIdx.y * 64 * TWO_D)
                      : (v10_hs + (size_t)(blockIdx.y - 2) * 64 * TWO_D);

    // staging: 64 rows x 32 k per tile; 2 threads/row, 16 k each
    const int st_row = tid >> 1;            // 0..63
    const int st_k16 = (tid & 1) * 16;      // 0 or 16
    const float* aSeg = Arow + (size_t)st_row * D_IN + kOff + st_k16;
    const float* bSeg = W1 + (size_t)(jBase + st_row) * TWO_D + wOff + st_k16;

    float4 pa[4], pb[4];
    #define V10_PREFETCH(kb) do {                                   \
        pa[0] = *(const float4*)(aSeg + (kb));                      \
        pa[1] = *(const float4*)(aSeg + (kb) + 4);                  \
        pa[2] = *(const float4*)(aSeg + (kb) + 8);                  \
        pa[3] = *(const float4*)(aSeg + (kb) + 12);                 \
        pb[0] = *(const float4*)(bSeg + (kb));                      \
        pb[1] = *(const float4*)(bSeg + (kb) + 4);                  \
        pb[2] = *(const float4*)(bSeg + (kb) + 8);                  \
        pb[3] = *(const float4*)(bSeg + (kb) + 12);                 \
    } while (0)

    // (c, c+4) pair interleave within each 8-k group
    #define V10_STAGE1(dst, v0, v1) do {                                          \
        float2 p;                                                                 \
        p.x = v10_tf32((v0).x); p.y = v10_tf32((v1).x); *(float2*)((dst) + 0) = p;\
        p.x = v10_tf32((v0).y); p.y = v10_tf32((v1).y); *(float2*)((dst) + 2) = p;\
        p.x = v10_tf32((v0).z); p.y = v10_tf32((v1).z); *(float2*)((dst) + 4) = p;\
        p.x = v10_tf32((v0).w); p.y = v10_tf32((v1).w); *(float2*)((dst) + 6) = p;\
    } while (0)

    #define V10_STAGE(buf) do {                                                   \
        float* ap = As + ((buf) * 64 + st_row) * V10_ST + st_k16;                 \
        V10_STAGE1(ap,     pa[0], pa[1]);                                         \
        V10_STAGE1(ap + 8, pa[2], pa[3]);                                         \
        float* bp = Bs + ((buf) * 64 + st_row) * V10_ST + st_k16;                 \
        V10_STAGE1(bp,     pb[0], pb[1]);                                         \
        V10_STAGE1(bp + 8, pb[2], pb[3]);                                         \
    } while (0)

    float d[2][4][4] = {};

    V10_PREFETCH(0);
    V10_STAGE(0);
    V10_PREFETCH(32);

    for (int kt = 0; kt < 12; kt++) {
        const int buf = kt & 1;
        __syncthreads();                       // buf fully staged by all threads
        if (kt < 11) {
            V10_STAGE(buf ^ 1);                // overlaps with compute below
            if (kt < 10) V10_PREFETCH((kt + 2) * 32);
        }

        const float* Ab = As + buf * 64 * V10_ST;
        const float* Bb = Bs + buf * 64 * V10_ST;
        #pragma unroll
        for (int s = 0; s < 4; s++) {
            unsigned afr[2][4];
            #pragma unroll
            for (int mf = 0; mf < 2; mf++) {
                const int r0 = warpM * 32 + mf * 16 + g;
                float2 p0 = *(const float2*)(Ab + r0 * V10_ST + s * 8 + t * 2);
                float2 p1 = *(const float2*)(Ab + (r0 + 8) * V10_ST + s * 8 + t * 2);
                afr[mf][0] = __float_as_uint(p0.x);
                afr[mf][1] = __float_as_uint(p1.x);
                afr[mf][2] = __float_as_uint(p0.y);
                afr[mf][3] = __float_as_uint(p1.y);
            }
            #pragma unroll
            for (int nf = 0; nf < 4; nf++) {
                const int n = warpN * 32 + nf * 8 + g;
                float2 q = *(const float2*)(Bb + n * V10_ST + s * 8 + t * 2);
                unsigned bfr[2] = { __float_as_uint(q.x), __float_as_uint(q.y) };
                v10_mma(d[0][nf], afr[0], bfr);
                v10_mma(d[1][nf], afr[1], bfr);
            }
        }
    }

    // ---- split-K pair reduction ----
    float* P = (z ? v10_p1 : v10_p0) + (size_t)tileIdx * 4096;
    #pragma unroll
    for (int mf = 0; mf < 2; mf++) {
        const int r0 = warpM * 32 + mf * 16 + g;
        #pragma unroll
        for (int nf = 0; nf < 4; nf++) {
            const int c0 = warpN * 32 + nf * 8 + t * 2;
            *(float2*)(P + r0 * 64 + c0)       = make_float2(d[mf][nf][0], d[mf][nf][1]);
            *(float2*)(P + (r0 + 8) * 64 + c0) = make_float2(d[mf][nf][2], d[mf][nf][3]);
        }
    }
    __threadfence();
    if (tid == 0) sSecond = (atomicAdd(&v10_cnt[tileIdx], 1u) == 1u);
    __syncthreads();
    if (!sSecond) return;
    __threadfence();   // acquire: peer partial visible

    const float* O = (z ? v10_p0 : v10_p1) + (size_t)tileIdx * 4096;
    #pragma unroll
    for (int mf = 0; mf < 2; mf++) {
        const int r0 = warpM * 32 + mf * 16 + g;
        #pragma unroll
        for (int nf = 0; nf < 4; nf++) {
            const int c0 = warpN * 32 + nf * 8 + t * 2;
            float2 o0 = *(const float2*)(O + r0 * 64 + c0);
            float2 o1 = *(const float2*)(O + (r0 + 8) * 64 + c0);
            float2 bias = make_float2(0.f, 0.f);
            if (isQ) bias = *(const float2*)(b1 + jBase + c0);
            float2 v0 = make_float2(d[mf][nf][0] + o0.x + bias.x,
                                    d[mf][nf][1] + o0.y + bias.y);
            float2 v1 = make_float2(d[mf][nf][2] + o1.x + bias.x,
                                    d[mf][nf][3] + o1.y + bias.y);
            *(float2*)(Crow + (size_t)r0 * TWO_D + jBase + c0)       = v0;
            *(float2*)(Crow + (size_t)(r0 + 8) * TWO_D + jBase + c0) = v1;
        }
    }
    if (tid == 0) v10_cnt[tileIdx] = 0;   // reset for graph replay
}

// ---------------------------------------------------------------------------
// Scores partial, packed f32x2 + ALU-pipe relu (identical to passing R7):
//   part[z][q][s] = sum_{j in chunk z} relu(hq[q][j]+hs[s][j]) * w2[j]
// grid = (8, 4, JCHUNKS=8), 256 threads.
// ---------------------------------------------------------------------------
__global__ void v10_scores(const float* __restrict__ W2)
{
    __shared__ __align__(16) float2 Aq2[8][34];
    __shared__ __align__(16) float2 Bs2[8][66];
    __shared__ float2 ws2[8];

    const int tid    = threadIdx.x;
    const int sBase  = blockIdx.x * 64;
    const int qBase  = blockIdx.y * 32;
    const int jcBase = blockIdx.z * JPER;
    const int ty = tid >> 4;
    const int tx = tid & 15;

    const int aq_q  = tid >> 3;
    const int aq_jp = tid & 7;
    const float* hqPtr = v10_hq + (size_t)(qBase + aq_q) * TWO_D + jcBase + aq_jp * 2;
    const int bs_s  = tid >> 2;
    const int bs_jp = (tid & 3) * 2;
    const float* hsPtr = v10_hs + (size_t)(sBase + bs_s) * TWO_D + jcBase + bs_jp * 2;

    double dacc[2][4] = {};
    ull acc2[2][4] = {};

    for (int jt = 0; jt < JPER; jt += 16) {
        float2 aval = *(const float2*)(hqPtr + jt);
        float4 bval = *(const float4*)(hsPtr + jt);
        float2 wval = make_float2(0.f, 0.f);
        if (tid < 8) wval = *(const float2*)(W2 + jcBase + jt + tid * 2);
        __syncthreads();
        Aq2[aq_jp][aq_q] = aval;
        Bs2[bs_jp][bs_s]     = make_float2(bval.x, bval.y);
        Bs2[bs_jp + 1][bs_s] = make_float2(bval.z, bval.w);
        if (tid < 8) ws2[tid] = wval;
        __syncthreads();

        #pragma unroll
        for (int jp = 0; jp < 8; jp++) {
            const ull w2v = *(const ull*)&ws2[jp];
            const ull a0  = *(const ull*)&Aq2[jp][ty * 2];
            const ull a1  = *(const ull*)&Aq2[jp][ty * 2 + 1];
            #pragma unroll
            for (int l = 0; l < 4; l++) {
                const ull bv = *(const ull*)&Bs2[jp][tx + l * 16];
                ull t0; V10_ADD2(t0, a0, bv);
                t0 = v10_relu2(t0);
                V10_FMA2(acc2[0][l], t0, w2v);
                ull t1; V10_ADD2(t1, a1, bv);
                t1 = v10_relu2(t1);
                V10_FMA2(acc2[1][l], t1, w2v);
            }
        }

        if ((jt & 63) == 48) {
            #pragma unroll
            for (int i = 0; i < 2; i++)
                #pragma unroll
                for (int l = 0; l < 4; l++) {
                    unsigned lo, hi;
                    asm("mov.b64 {%0,%1}, %2;" : "=r"(lo), "=r"(hi) : "l"(acc2[i][l]));
                    dacc[i][l] += (double)(__uint_as_float(lo) + __uint_as_float(hi));
                    acc2[i][l] = 0ull;
                }
        }
    }

    double* outp = v10_part + (size_t)blockIdx.z * (Q_N * S_N);
    #pragma unroll
    for (int i = 0; i < 2; i++)
        #pragma unroll
        for (int l = 0; l < 4; l++)
            outp[(size_t)(qBase + ty * 2 + i) * S_N + sBase + tx + l * 16] = dacc[i][l];
}

// ---------------------------------------------------------------------------
// Per-query aggregate + softmax + pred + merged final loss reduction (ticket).
// grid = 128 blocks, 128 threads. All fp64, deterministic.
// ---------------------------------------------------------------------------
__global__ void v10_agg(const int* __restrict__ labels,
                        const int* __restrict__ targets,
                        const float* __restrict__ b2,
                        float* __restrict__ out, int out_size)
{
    __shared__ double sc[S_N];
    __shared__ int    lab[S_N];
    __shared__ double aggv[C_N];
    __shared__ double redv[C_N];
    __shared__ int    redi[C_N];
    __shared__ double rede[C_N];
    __shared__ int    isLast;
    __shared__ double lred[Q_N];

    const int q   = blockIdx.x;
    const int tid = threadIdx.x;
    const double b2v = (double)b2[0];

    for (int s = tid; s < S_N; s += 128) lab[s] = labels[s];

    for (int s = tid; s < S_N; s += 128) {
        double v = 0.0;
        #pragma unroll
        for (int z = 0; z < JCHUNKS; z++)
            v += v10_part[(size_t)z * (Q_N * S_N) + (size_t)q * S_N + s];
        sc[s] = v + b2v;
    }
    __syncthreads();

    if (tid < C_N) {
        double ssum = 0.0;
        int cnt = 0;
        for (int s = 0; s < S_N; s++)
            if (lab[s] == tid) { ssum += sc[s]; cnt++; }
        aggv[tid] = ssum / (double)(cnt > 1 ? cnt : 1);
        redv[tid] = aggv[tid];
        redi[tid] = tid;
    }
    __syncthreads();

    #pragma unroll
    for (int off = C_N / 2; off > 0; off >>= 1) {
        if (tid < off) {
            if (redv[tid + off] > redv[tid] ||
                (redv[tid + off] == redv[tid] && redi[tid + off] < redi[tid])) {
                redv[tid] = redv[tid + off];
                redi[tid] = redi[tid + off];
            }
        }
        __syncthreads();
    }
    const double mx = redv[0];
    const int    am = redi[0];

    if (tid < C_N) rede[tid] = exp(aggv[tid] - mx);
    __syncthreads();
    #pragma unroll
    for (int off = C_N / 2; off > 0; off >>= 1) {
        if (tid < off) rede[tid] += rede[tid + off];
        __syncthreads();
    }

    if (tid == 0) {
        const int tgt = targets[q];
        const double logp = aggv[tgt] - mx - log(rede[0]);
        v10_loss[q] = -logp;
        if (1 + q < out_size) out[1 + q] = (am == tgt) ? 1.0f : 0.0f;
        __threadfence();
        unsigned tk = atomicAdd(&v10_ticket, 1u);
        isLast = (tk == (unsigned)(Q_N - 1));
    }
    __syncthreads();

    if (isLast) {
        __threadfence();
        lred[tid] = v10_loss[tid];
        __syncthreads();
        #pragma unroll
        for (int off = Q_N / 2; off > 0; off >>= 1) {
            if (tid < off) lred[tid] += lred[tid + off];
            __syncthreads();
        }
        if (tid == 0) {
            if (out_size > 0) out[0] = (float)(lred[0] / (double)Q_N);
            v10_ticket = 0;
        }
    }
}

// ---------------------------------------------------------------------------
extern "C" void kernel_launch(void* const* d_in, const int* in_sizes, int n_in,
                              void* d_out, int out_size)
{
    const float* query   = (const float*)d_in[0];
    const float* support = (const float*)d_in[1];
    const float* W1      = (const float*)d_in[2];
    const float* b1      = (const float*)d_in[3];
    const float* W2      = (const float*)d_in[4];
    const float* b2      = (const float*)d_in[5];
    const int*   labels  = (const int*)  d_in[6];
    const int*   targets = (const int*)  d_in[7];
    (void)in_sizes; (void)n_in;

    float* out = (float*)d_out;

    cudaFuncSetAttribute(v10_gemm, cudaFuncAttributeMaxDynamicSharedMemorySize, V10_SMEM);

    v10_gemm  <<<dim3(24, 10, 2), 128, V10_SMEM>>>(query, support, W1, b1);
    v10_scores<<<dim3(S_N/64, Q_N/32, JCHUNKS), 256>>>(W2);
    v10_agg   <<<Q_N, 128>>>(labels, targets, b2, out, out_size);
}

// round 11
// speedup vs baseline: 1.1343x; 1.1343x over previous
#include <cuda_runtime.h>
#include <math.h>
#include <stdint.h>

#define D_IN   768
#define TWO_D  1536
#define Q_N    128
#define S_N    512
#define C_N    64
#define JCHUNKS 8
#define JPER   (TWO_D / JCHUNKS)    /* 192 */
#define KSPLIT 384

typedef unsigned long long ull;

// Scratch (device globals: allocation-free per harness rules)
__device__ float    v11_hq0[Q_N * TWO_D];            // hq partial k[0,384) (+b1)
__device__ float    v11_hq1[Q_N * TWO_D];            // hq partial k[384,768)
__device__ float    v11_hs0[S_N * TWO_D];
__device__ float    v11_hs1[S_N * TWO_D];
__device__ double   v11_part[JCHUNKS * Q_N * S_N];   // fp64 partial scores per j-chunk
__device__ double   v11_loss[Q_N];
__device__ unsigned v11_ticket = 0;

// fp32 -> tf32 RNA rounding (matches cuBLAS TF32 input quantization = reference)
__device__ __forceinline__ float v11_tf32(float x) {
    unsigned u;
    asm("cvt.rna.tf32.f32 %0, %1;" : "=r"(u) : "f"(x));
    return __uint_as_float(u);
}

// m16n8k8 tf32 mma (base ISA, sm_80+)
__device__ __forceinline__ void v11_mma(float d[4], const unsigned a[4], const unsigned b[2]) {
    asm volatile(
        "mma.sync.aligned.m16n8k8.row.col.f32.tf32.tf32.f32 "
        "{%0,%1,%2,%3}, {%4,%5,%6,%7}, {%8,%9}, {%0,%1,%2,%3};"
        : "+f"(d[0]), "+f"(d[1]), "+f"(d[2]), "+f"(d[3])
        : "r"(a[0]), "r"(a[1]), "r"(a[2]), "r"(a[3]), "r"(b[0]), "r"(b[1]));
}

// packed f32x2 (base ISA on sm_100+ family; SASS FADD2/FFMA2)
#define V11_ADD2(d, a, b) \
    asm("add.rn.f32x2 %0, %1, %2;" : "=l"(d) : "l"(a), "l"(b))
#define V11_FMA2(acc, t, w) \
    asm("fma.rn.f32x2 %0, %1, %2, %0;" : "+l"(acc) : "l"(t), "l"(w))

// packed relu on the ALU pipe (IMAX): valid for all non-NaN floats
__device__ __forceinline__ ull v11_relu2(ull t) {
    unsigned lo, hi;
    asm("mov.b64 {%0,%1}, %2;" : "=r"(lo), "=r"(hi) : "l"(t));
    int l2 = max((int)lo, 0);
    int h2 = max((int)hi, 0);
    ull r;
    asm("mov.b64 %0, {%1,%2};" : "=l"(r) : "r"((unsigned)l2), "r"((unsigned)h2));
    return r;
}

// ---------------------------------------------------------------------------
// TF32 tensor-core GEMM, split-K x2 (VERBATIM R8 = best measured, 26.1 us):
// CTA 64m x 128n x K384; 12 double-buffered k-tiles of 32, one barrier/iter.
// 8 warps (2M x 4N), warp tile 32x32. grid = (12, 10, 2), occupancy 2.
// ---------------------------------------------------------------------------
#define V11_ST     40
#define V11_ASZ    (2 * 64 * V11_ST)
#define V11_BSZ    (2 * 128 * V11_ST)
#define V11_SMEM   ((V11_ASZ + V11_BSZ) * 4)

__global__ void __launch_bounds__(256, 2)
v11_gemm(const float* __restrict__ query,
         const float* __restrict__ support,
         const float* __restrict__ W1,
         const float* __restrict__ b1)
{
    extern __shared__ __align__(16) float smem[];
    float* As = smem;               // [2][64][40]
    float* Bs = smem + V11_ASZ;     // [2][128][40]

    const int tid  = threadIdx.x;
    const int lane = tid & 31;
    const int wid  = tid >> 5;
    const int warpM = wid & 1;
    const int warpN = wid >> 1;
    const int g = lane >> 2;
    const int t = lane & 3;

    const int  z    = blockIdx.z;
    const int  kOff = z * KSPLIT;
    const bool isQ  = (blockIdx.y < 2);
    const float* Arow = isQ ? (query + (size_t)blockIdx.y * 64 * D_IN)
                            : (support + (size_t)(blockIdx.y - 2) * 64 * D_IN);
    const int   wOff  = (isQ ? 0 : D_IN) + kOff;
    const int   jBase = blockIdx.x * 128;
    float* Hq = z ? v11_hq1 : v11_hq0;
    float* Hs = z ? v11_hs1 : v11_hs0;
    float* Crow = isQ ? (Hq + (size_t)blockIdx.y * 64 * TWO_D)
                      : (Hs + (size_t)(blockIdx.y - 2) * 64 * TWO_D);

    const int a_row = tid >> 2, a_ks = tid & 3;
    const int b_row0 = tid >> 2, b_ks0 = tid & 3;
    const int b_row1 = (tid + 256) >> 2, b_ks1 = tid & 3;
    const float* aSeg  = Arow + (size_t)a_row * D_IN + kOff + a_ks * 8;
    const float* bSeg0 = W1 + (size_t)(jBase + b_row0) * TWO_D + wOff + b_ks0 * 8;
    const float* bSeg1 = W1 + (size_t)(jBase + b_row1) * TWO_D + wOff + b_ks1 * 8;

    float4 pa0, pa1, pb00, pb01, pb10, pb11;
    #define V11_PREFETCH(kb) do {                                   \
        pa0  = *(const float4*)(aSeg  + (kb));                      \
        pa1  = *(const float4*)(aSeg  + (kb) + 4);                  \
        pb00 = *(const float4*)(bSeg0 + (kb));                      \
        pb01 = *(const float4*)(bSeg0 + (kb) + 4);                  \
        pb10 = *(const float4*)(bSeg1 + (kb));                      \
        pb11 = *(const float4*)(bSeg1 + (kb) + 4);                  \
    } while (0)

    #define V11_STAGE(buf) do {                                                     \
        float* ap = As + ((buf) * 64 + a_row) * V11_ST + a_ks * 8;                  \
        float2 p;                                                                   \
        p.x = v11_tf32(pa0.x); p.y = v11_tf32(pa1.x); *(float2*)(ap + 0) = p;       \
        p.x = v11_tf32(pa0.y); p.y = v11_tf32(pa1.y); *(float2*)(ap + 2) = p;       \
        p.x = v11_tf32(pa0.z); p.y = v11_tf32(pa1.z); *(float2*)(ap + 4) = p;       \
        p.x = v11_tf32(pa0.w); p.y = v11_tf32(pa1.w); *(float2*)(ap + 6) = p;       \
        float* bp = Bs + ((buf) * 128 + b_row0) * V11_ST + b_ks0 * 8;               \
        p.x = v11_tf32(pb00.x); p.y = v11_tf32(pb01.x); *(float2*)(bp + 0) = p;     \
        p.x = v11_tf32(pb00.y); p.y = v11_tf32(pb01.y); *(float2*)(bp + 2) = p;     \
        p.x = v11_tf32(pb00.z); p.y = v11_tf32(pb01.z); *(float2*)(bp + 4) = p;     \
        p.x = v11_tf32(pb00.w); p.y = v11_tf32(pb01.w); *(float2*)(bp + 6) = p;     \
        bp = Bs + ((buf) * 128 + b_row1) * V11_ST + b_ks1 * 8;                      \
        p.x = v11_tf32(pb10.x); p.y = v11_tf32(pb11.x); *(float2*)(bp + 0) = p;     \
        p.x = v11_tf32(pb10.y); p.y = v11_tf32(pb11.y); *(float2*)(bp + 2) = p;     \
        p.x = v11_tf32(pb10.z); p.y = v11_tf32(pb11.z); *(float2*)(bp + 4) = p;     \
        p.x = v11_tf32(pb10.w); p.y = v11_tf32(pb11.w); *(float2*)(bp + 6) = p;     \
    } while (0)

    float d[2][4][4] = {};

    V11_PREFETCH(0);
    V11_STAGE(0);
    V11_PREFETCH(32);

    for (int kt = 0; kt < 12; kt++) {
        const int buf = kt & 1;
        __syncthreads();
        if (kt < 11) {
            V11_STAGE(buf ^ 1);
            if (kt < 10) V11_PREFETCH((kt + 2) * 32);
        }

        const float* Ab = As + buf * 64 * V11_ST;
        const float* Bb = Bs + buf * 128 * V11_ST;
        #pragma unroll
        for (int s = 0; s < 4; s++) {
            unsigned afr[2][4];
            #pragma unroll
            for (int mf = 0; mf < 2; mf++) {
                const int r0 = warpM * 32 + mf * 16 + g;
                float2 p0 = *(const float2*)(Ab + r0 * V11_ST + s * 8 + t * 2);
                float2 p1 = *(const float2*)(Ab + (r0 + 8) * V11_ST + s * 8 + t * 2);
                afr[mf][0] = __float_as_uint(p0.x);
                afr[mf][1] = __float_as_uint(p1.x);
                afr[mf][2] = __float_as_uint(p0.y);
                afr[mf][3] = __float_as_uint(p1.y);
            }
            #pragma unroll
            for (int nf = 0; nf < 4; nf++) {
                const int n = warpN * 32 + nf * 8 + g;
                float2 q = *(const float2*)(Bb + n * V11_ST + s * 8 + t * 2);
                unsigned bfr[2] = { __float_as_uint(q.x), __float_as_uint(q.y) };
                v11_mma(d[0][nf], afr[0], bfr);
                v11_mma(d[1][nf], afr[1], bfr);
            }
        }
    }

    const bool addBias = isQ && (z == 0);
    #pragma unroll
    for (int mf = 0; mf < 2; mf++) {
        const int r0 = warpM * 32 + mf * 16 + g;
        #pragma unroll
        for (int nf = 0; nf < 4; nf++) {
            const int c0 = jBase + warpN * 32 + nf * 8 + t * 2;
            float2 bias = make_float2(0.f, 0.f);
            if (addBias) bias = *(const float2*)(b1 + c0);
            float2 v0 = make_float2(d[mf][nf][0] + bias.x, d[mf][nf][1] + bias.y);
            float2 v1 = make_float2(d[mf][nf][2] + bias.x, d[mf][nf][3] + bias.y);
            *(float2*)(Crow + (size_t)r0 * TWO_D + c0)       = v0;
            *(float2*)(Crow + (size_t)(r0 + 8) * TWO_D + c0) = v1;
        }
    }
}

// ---------------------------------------------------------------------------
// Scores partial v11: per-thread 2q x 8s f32x2 tile (high fma density),
// double-buffered staging w/ register prefetch; split-K pair summed in staging.
//   part[z][q][s] = sum_{j in chunk z} relu(hq[q][j]+hs[s][j]) * w2[j]
// Block 32q x 128s, 256 threads. grid = (S/128=4, Q/32=4, JCHUNKS=8) = 128.
// fp32 packed accumulation over the full 192-j chunk, one fp64 convert at end.
// ---------------------------------------------------------------------------
__global__ void __launch_bounds__(256, 2)
v11_scores(const float* __restrict__ W2)
{
    __shared__ __align__(16) float2 Aq2[2][8][34];    // [buf][jp][q]
    __shared__ __align__(16) float2 Bs2[2][8][130];   // [buf][jp][s]
    __shared__ float2 ws2[2][8];

    const int tid    = threadIdx.x;
    const int sBase  = blockIdx.x * 128;
    const int qBase  = blockIdx.y * 32;
    const int jcBase = blockIdx.z * JPER;
    const int ty = tid >> 4;      // 0..15 -> q rows ty*2, ty*2+1
    const int tx = tid & 15;      // s cols tx + l*16, l=0..7

    // A staging: 32 q x 8 jp (one f32x2 per thread)
    const int aq_q  = tid >> 3;          // 0..31
    const int aq_jp = tid & 7;
    const size_t hqOff = (size_t)(qBase + aq_q) * TWO_D + jcBase + aq_jp * 2;
    // B staging: 128 s x 8 jp (4 jp per thread: 8 consecutive j)
    const int bs_s  = tid >> 1;          // 0..127
    const int bs_h  = (tid & 1) * 8;     // j offset 0 or 8
    const int bs_jp = bs_h >> 1;         // jp base 0 or 4
    const size_t hsOff = (size_t)(sBase + bs_s) * TWO_D + jcBase + bs_h;

    float2 pa0, pa1, pw;
    float4 pb00, pb01, pb10, pb11;

    #define V11S_PRE(jt) do {                                          \
        pa0  = *(const float2*)(v11_hq0 + hqOff + (jt));               \
        pa1  = *(const float2*)(v11_hq1 + hqOff + (jt));               \
        pb00 = *(const float4*)(v11_hs0 + hsOff + (jt));               \
        pb01 = *(const float4*)(v11_hs0 + hsOff + (jt) + 4);           \
        pb10 = *(const float4*)(v11_hs1 + hsOff + (jt));               \
        pb11 = *(const float4*)(v11_hs1 + hsOff + (jt) + 4);           \
        if (tid < 8) pw = *(const float2*)(W2 + jcBase + (jt) + tid * 2); \
    } while (0)

    #define V11S_STAGE(buf) do {                                                     \
        Aq2[buf][aq_jp][aq_q] = make_float2(pa0.x + pa1.x, pa0.y + pa1.y);            \
        Bs2[buf][bs_jp + 0][bs_s] = make_float2(pb00.x + pb10.x, pb00.y + pb10.y);    \
        Bs2[buf][bs_jp + 1][bs_s] = make_float2(pb00.z + pb10.z, pb00.w + pb10.w);    \
        Bs2[buf][bs_jp + 2][bs_s] = make_float2(pb01.x + pb11.x, pb01.y + pb11.y);    \
        Bs2[buf][bs_jp + 3][bs_s] = make_float2(pb01.z + pb11.z, pb01.w + pb11.w);    \
        if (tid < 8) ws2[buf][tid] = pw;                                              \
    } while (0)

    ull acc2[2][8] = {};

    V11S_PRE(0);
    V11S_STAGE(0);
    V11S_PRE(16);

    for (int it = 0; it < 12; it++) {
        const int buf = it & 1;
        __syncthreads();
        if (it < 11) {
            V11S_STAGE(buf ^ 1);
            if (it < 10) V11S_PRE((it + 2) * 16);
        }

        #pragma unroll
        for (int jp = 0; jp < 8; jp++) {
            const ull w2v = *(const ull*)&ws2[buf][jp];
            const ull a0  = *(const ull*)&Aq2[buf][jp][ty * 2];
            const ull a1  = *(const ull*)&Aq2[buf][jp][ty * 2 + 1];
            #pragma unroll
            for (int l = 0; l < 8; l++) {
                const ull bv = *(const ull*)&Bs2[buf][jp][tx + l * 16];
                ull t0; V11_ADD2(t0, a0, bv);
                t0 = v11_relu2(t0);
                V11_FMA2(acc2[0][l], t0, w2v);
                ull t1; V11_ADD2(t1, a1, bv);
                t1 = v11_relu2(t1);
                V11_FMA2(acc2[1][l], t1, w2v);
            }
        }
    }

    double* outp = v11_part + (size_t)blockIdx.z * (Q_N * S_N);
    #pragma unroll
    for (int i = 0; i < 2; i++)
        #pragma unroll
        for (int l = 0; l < 8; l++) {
            unsigned lo, hi;
            asm("mov.b64 {%0,%1}, %2;" : "=r"(lo), "=r"(hi) : "l"(acc2[i][l]));
            outp[(size_t)(qBase + ty * 2 + i) * S_N + sBase + tx + l * 16] =
                (double)(__uint_as_float(lo) + __uint_as_float(hi));
        }
}

// ---------------------------------------------------------------------------
// Per-query aggregate + softmax + pred + merged final loss reduction (ticket).
// grid = 128 blocks, 128 threads. All fp64, deterministic.
// ---------------------------------------------------------------------------
__global__ void v11_agg(const int* __restrict__ labels,
                        const int* __restrict__ targets,
                        const float* __restrict__ b2,
                        float* __restrict__ out, int out_size)
{
    __shared__ double sc[S_N];
    __shared__ int    lab[S_N];
    __shared__ double aggv[C_N];
    __shared__ double redv[C_N];
    __shared__ int    redi[C_N];
    __shared__ double rede[C_N];
    __shared__ int    isLast;
    __shared__ double lred[Q_N];

    const int q   = blockIdx.x;
    const int tid = threadIdx.x;
    const double b2v = (double)b2[0];

    for (int s = tid; s < S_N; s += 128) lab[s] = labels[s];

    for (int s = tid; s < S_N; s += 128) {
        double v = 0.0;
        #pragma unroll
        for (int z = 0; z < JCHUNKS; z++)
            v += v11_part[(size_t)z * (Q_N * S_N) + (size_t)q * S_N + s];
        sc[s] = v + b2v;
    }
    __syncthreads();

    if (tid < C_N) {
        double ssum = 0.0;
        int cnt = 0;
        for (int s = 0; s < S_N; s++)
            if (lab[s] == tid) { ssum += sc[s]; cnt++; }
        aggv[tid] = ssum / (double)(cnt > 1 ? cnt : 1);
        redv[tid] = aggv[tid];
        redi[tid] = tid;
    }
    __syncthreads();

    #pragma unroll
    for (int off = C_N / 2; off > 0; off >>= 1) {
        if (tid < off) {
            if (redv[tid + off] > redv[tid] ||
                (redv[tid + off] == redv[tid] && redi[tid + off] < redi[tid])) {
                redv[tid] = redv[tid + off];
                redi[tid] = redi[tid + off];
            }
        }
        __syncthreads();
    }
    const double mx = redv[0];
    const int    am = redi[0];

    if (tid < C_N) rede[tid] = exp(aggv[tid] - mx);
    __syncthreads();
    #pragma unroll
    for (int off = C_N / 2; off > 0; off >>= 1) {
        if (tid < off) rede[tid] += rede[tid + off];
        __syncthreads();
    }

    if (tid == 0) {
        const int tgt = targets[q];
        const double logp = aggv[tgt] - mx - log(rede[0]);
        v11_loss[q] = -logp;
        if (1 + q < out_size) out[1 + q] = (am == tgt) ? 1.0f : 0.0f;
        __threadfence();
        unsigned tk = atomicAdd(&v11_ticket, 1u);
        isLast = (tk == (unsigned)(Q_N - 1));
    }
    __syncthreads();

    if (isLast) {
        __threadfence();
        lred[tid] = v11_loss[tid];
        __syncthreads();
        #pragma unroll
        for (int off = Q_N / 2; off > 0; off >>= 1) {
            if (tid < off) lred[tid] += lred[tid + off];
            __syncthreads();
        }
        if (tid == 0) {
            if (out_size > 0) out[0] = (float)(lred[0] / (double)Q_N);
            v11_ticket = 0;
        }
    }
}

// ---------------------------------------------------------------------------
extern "C" void kernel_launch(void* const* d_in, const int* in_sizes, int n_in,
                              void* d_out, int out_size)
{
    const float* query   = (const float*)d_in[0];
    const float* support = (const float*)d_in[1];
    const float* W1      = (const float*)d_in[2];
    const float* b1      = (const float*)d_in[3];
    const float* W2      = (const float*)d_in[4];
    const float* b2      = (const float*)d_in[5];
    const int*   labels  = (const int*)  d_in[6];
    const int*   targets = (const int*)  d_in[7];
    (void)in_sizes; (void)n_in;

    float* out = (float*)d_out;

    cudaFuncSetAttribute(v11_gemm, cudaFuncAttributeMaxDynamicSharedMemorySize, V11_SMEM);

    v11_gemm  <<<dim3(12, 10, 2), 256, V11_SMEM>>>(query, support, W1, b1);
    v11_scores<<<dim3(4, 4, JCHUNKS), 256>>>(W2);
    v11_agg   <<<Q_N, 128>>>(labels, targets, b2, out, out_size);
}

// round 12
// speedup vs baseline: 1.3508x; 1.1908x over previous
#include <cuda_runtime.h>
#include <math.h>
#include <stdint.h>

#define D_IN   768
#define TWO_D  1536
#define Q_N    128
#define S_N    512
#define C_N    64
#define JCHUNKS 8
#define JPER   (TWO_D / JCHUNKS)    /* 192 */
#define KSPLIT 384
#define NCB    32                   /* chunk-blocks = JCHUNKS * 4 s-tiles */

typedef unsigned long long ull;

// Scratch (device globals: allocation-free per harness rules)
__device__ float    v12_hq0[Q_N * TWO_D];
__device__ float    v12_hq1[Q_N * TWO_D];
__device__ float    v12_hs0[S_N * TWO_D];
__device__ float    v12_hs1[S_N * TWO_D];
__device__ double   v12_part2[NCB * Q_N * C_N];     // class-binned partials (2 MB)
__device__ double   v12_loss[Q_N];
__device__ unsigned v12_ticket = 0;

// fp32 -> tf32 RNA rounding (matches cuBLAS TF32 input quantization = reference)
__device__ __forceinline__ float v12_tf32(float x) {
    unsigned u;
    asm("cvt.rna.tf32.f32 %0, %1;" : "=r"(u) : "f"(x));
    return __uint_as_float(u);
}

// m16n8k8 tf32 mma (base ISA, sm_80+)
__device__ __forceinline__ void v12_mma(float d[4], const unsigned a[4], const unsigned b[2]) {
    asm volatile(
        "mma.sync.aligned.m16n8k8.row.col.f32.tf32.tf32.f32 "
        "{%0,%1,%2,%3}, {%4,%5,%6,%7}, {%8,%9}, {%0,%1,%2,%3};"
        : "+f"(d[0]), "+f"(d[1]), "+f"(d[2]), "+f"(d[3])
        : "r"(a[0]), "r"(a[1]), "r"(a[2]), "r"(a[3]), "r"(b[0]), "r"(b[1]));
}

#define V12_ADD2(d, a, b) \
    asm("add.rn.f32x2 %0, %1, %2;" : "=l"(d) : "l"(a), "l"(b))
#define V12_FMA2(acc, t, w) \
    asm("fma.rn.f32x2 %0, %1, %2, %0;" : "+l"(acc) : "l"(t), "l"(w))

// packed relu on the ALU pipe (IMAX): valid for all non-NaN floats
__device__ __forceinline__ ull v12_relu2(ull t) {
    unsigned lo, hi;
    asm("mov.b64 {%0,%1}, %2;" : "=r"(lo), "=r"(hi) : "l"(t));
    int l2 = max((int)lo, 0);
    int h2 = max((int)hi, 0);
    ull r;
    asm("mov.b64 %0, {%1,%2};" : "=l"(r) : "l"((ull)0), "r"((unsigned)h2));
    // (re-pack lo too)
    asm("mov.b64 %0, {%1,%2};" : "=l"(r) : "r"((unsigned)l2), "r"((unsigned)h2));
    return r;
}

// ---------------------------------------------------------------------------
// TF32 tensor-core GEMM, split-K x2 (VERBATIM best-measured R8/R11 config).
// CTA 64m x 128n x K384; 12 double-buffered k-tiles of 32, one barrier/iter.
// 8 warps (2M x 4N), warp tile 32x32. grid = (12, 10, 2), occupancy 2.
// ---------------------------------------------------------------------------
#define V12_ST     40
#define V12_ASZ    (2 * 64 * V12_ST)
#define V12_BSZ    (2 * 128 * V12_ST)
#define V12_SMEM   ((V12_ASZ + V12_BSZ) * 4)

__global__ void __launch_bounds__(256, 2)
v12_gemm(const float* __restrict__ query,
         const float* __restrict__ support,
         const float* __restrict__ W1,
         const float* __restrict__ b1)
{
    extern __shared__ __align__(16) float smem[];
    float* As = smem;
    float* Bs = smem + V12_ASZ;

    const int tid  = threadIdx.x;
    const int lane = tid & 31;
    const int wid  = tid >> 5;
    const int warpM = wid & 1;
    const int warpN = wid >> 1;
    const int g = lane >> 2;
    const int t = lane & 3;

    const int  z    = blockIdx.z;
    const int  kOff = z * KSPLIT;
    const bool isQ  = (blockIdx.y < 2);
    const float* Arow = isQ ? (query + (size_t)blockIdx.y * 64 * D_IN)
                            : (support + (size_t)(blockIdx.y - 2) * 64 * D_IN);
    const int   wOff  = (isQ ? 0 : D_IN) + kOff;
    const int   jBase = blockIdx.x * 128;
    float* Hq = z ? v12_hq1 : v12_hq0;
    float* Hs = z ? v12_hs1 : v12_hs0;
    float* Crow = isQ ? (Hq + (size_t)blockIdx.y * 64 * TWO_D)
                      : (Hs + (size_t)(blockIdx.y - 2) * 64 * TWO_D);

    const int a_row = tid >> 2, a_ks = tid & 3;
    const int b_row0 = tid >> 2, b_ks0 = tid & 3;
    const int b_row1 = (tid + 256) >> 2, b_ks1 = tid & 3;
    const float* aSeg  = Arow + (size_t)a_row * D_IN + kOff + a_ks * 8;
    const float* bSeg0 = W1 + (size_t)(jBase + b_row0) * TWO_D + wOff + b_ks0 * 8;
    const float* bSeg1 = W1 + (size_t)(jBase + b_row1) * TWO_D + wOff + b_ks1 * 8;

    float4 pa0, pa1, pb00, pb01, pb10, pb11;
    #define V12_PREFETCH(kb) do {                                   \
        pa0  = *(const float4*)(aSeg  + (kb));                      \
        pa1  = *(const float4*)(aSeg  + (kb) + 4);                  \
        pb00 = *(const float4*)(bSeg0 + (kb));                      \
        pb01 = *(const float4*)(bSeg0 + (kb) + 4);                  \
        pb10 = *(const float4*)(bSeg1 + (kb));                      \
        pb11 = *(const float4*)(bSeg1 + (kb) + 4);                  \
    } while (0)

    #define V12_STAGE(buf) do {                                                     \
        float* ap = As + ((buf) * 64 + a_row) * V12_ST + a_ks * 8;                  \
        float2 p;                                                                   \
        p.x = v12_tf32(pa0.x); p.y = v12_tf32(pa1.x); *(float2*)(ap + 0) = p;       \
        p.x = v12_tf32(pa0.y); p.y = v12_tf32(pa1.y); *(float2*)(ap + 2) = p;       \
        p.x = v12_tf32(pa0.z); p.y = v12_tf32(pa1.z); *(float2*)(ap + 4) = p;       \
        p.x = v12_tf32(pa0.w); p.y = v12_tf32(pa1.w); *(float2*)(ap + 6) = p;       \
        float* bp = Bs + ((buf) * 128 + b_row0) * V12_ST + b_ks0 * 8;               \
        p.x = v12_tf32(pb00.x); p.y = v12_tf32(pb01.x); *(float2*)(bp + 0) = p;     \
        p.x = v12_tf32(pb00.y); p.y = v12_tf32(pb01.y); *(float2*)(bp + 2) = p;     \
        p.x = v12_tf32(pb00.z); p.y = v12_tf32(pb01.z); *(float2*)(bp + 4) = p;     \
        p.x = v12_tf32(pb00.w); p.y = v12_tf32(pb01.w); *(float2*)(bp + 6) = p;     \
        bp = Bs + ((buf) * 128 + b_row1) * V12_ST + b_ks1 * 8;                      \
        p.x = v12_tf32(pb10.x); p.y = v12_tf32(pb11.x); *(float2*)(bp + 0) = p;     \
        p.x = v12_tf32(pb10.y); p.y = v12_tf32(pb11.y); *(float2*)(bp + 2) = p;     \
        p.x = v12_tf32(pb10.z); p.y = v12_tf32(pb11.z); *(float2*)(bp + 4) = p;     \
        p.x = v12_tf32(pb10.w); p.y = v12_tf32(pb11.w); *(float2*)(bp + 6) = p;     \
    } while (0)

    float d[2][4][4] = {};

    V12_PREFETCH(0);
    V12_STAGE(0);
    V12_PREFETCH(32);

    for (int kt = 0; kt < 12; kt++) {
        const int buf = kt & 1;
        __syncthreads();
        if (kt < 11) {
            V12_STAGE(buf ^ 1);
            if (kt < 10) V12_PREFETCH((kt + 2) * 32);
        }

        const float* Ab = As + buf * 64 * V12_ST;
        const float* Bb = Bs + buf * 128 * V12_ST;
        #pragma unroll
        for (int s = 0; s < 4; s++) {
            unsigned afr[2][4];
            #pragma unroll
            for (int mf = 0; mf < 2; mf++) {
                const int r0 = warpM * 32 + mf * 16 + g;
                float2 p0 = *(const float2*)(Ab + r0 * V12_ST + s * 8 + t * 2);
                float2 p1 = *(const float2*)(Ab + (r0 + 8) * V12_ST + s * 8 + t * 2);
                afr[mf][0] = __float_as_uint(p0.x);
                afr[mf][1] = __float_as_uint(p1.x);
                afr[mf][2] = __float_as_uint(p0.y);
                afr[mf][3] = __float_as_uint(p1.y);
            }
            #pragma unroll
            for (int nf = 0; nf < 4; nf++) {
                const int n = warpN * 32 + nf * 8 + g;
                float2 q = *(const float2*)(Bb + n * V12_ST + s * 8 + t * 2);
                unsigned bfr[2] = { __float_as_uint(q.x), __float_as_uint(q.y) };
                v12_mma(d[0][nf], afr[0], bfr);
                v12_mma(d[1][nf], afr[1], bfr);
            }
        }
    }

    const bool addBias = isQ && (z == 0);
    #pragma unroll
    for (int mf = 0; mf < 2; mf++) {
        const int r0 = warpM * 32 + mf * 16 + g;
        #pragma unroll
        for (int nf = 0; nf < 4; nf++) {
            const int c0 = jBase + warpN * 32 + nf * 8 + t * 2;
            float2 bias = make_float2(0.f, 0.f);
            if (addBias) bias = *(const float2*)(b1 + c0);
            float2 v0 = make_float2(d[mf][nf][0] + bias.x, d[mf][nf][1] + bias.y);
            float2 v1 = make_float2(d[mf][nf][2] + bias.x, d[mf][nf][3] + bias.y);
            *(float2*)(Crow + (size_t)r0 * TWO_D + c0)       = v0;
            *(float2*)(Crow + (size_t)(r0 + 8) * TWO_D + c0) = v1;
        }
    }
}

// ---------------------------------------------------------------------------
// Scores + class binning. Compute identical to passing R11; output phase bins
// the 32q x 128s chunk scores into 32q x 64c class partials using the sorted
// labels' contiguous class segments (fixed s-ascending order, deterministic).
// Dynamic smem overlay: staging (21KB) reused as fp64 score tile (33KB) +
// labels + segment table. grid = (4 s-tiles, 4 q-stripes, 8 j-chunks) = 128.
// ---------------------------------------------------------------------------
#define V12S_DYN   33824   /* bytes: scr 33024 + lab 512 + seg 260 + pad */

__global__ void __launch_bounds__(256, 2)
v12_scores(const float* __restrict__ W2, const int* __restrict__ labels)
{
    extern __shared__ __align__(16) char dyn[];
    // staging layout (phase 1)
    float2* Aq2 = (float2*)(dyn);                 // [2][8][34]
    float2* Bs2 = (float2*)(dyn + 4352);          // [2][8][130]
    float2* ws2 = (float2*)(dyn + 20992);         // [2][8]
    // post layout (phase 2, after barrier)
    double* scr  = (double*)(dyn);                // [32][129]
    int*    lab2 = (int*)(dyn + 33024);           // [128]
    int*    seg  = (int*)(dyn + 33536);           // [65]

    const int tid    = threadIdx.x;
    const int sBase  = blockIdx.x * 128;
    const int qBase  = blockIdx.y * 32;
    const int jcBase = blockIdx.z * JPER;
    const int ty = tid >> 4;      // q rows ty*2, ty*2+1
    const int tx = tid & 15;      // s cols tx + l*16, l=0..7

    const int aq_q  = tid >> 3;
    const int aq_jp = tid & 7;
    const size_t hqOff = (size_t)(qBase + aq_q) * TWO_D + jcBase + aq_jp * 2;
    const int bs_s  = tid >> 1;
    const int bs_h  = (tid & 1) * 8;
    const int bs_jp = bs_h >> 1;
    const size_t hsOff = (size_t)(sBase + bs_s) * TWO_D + jcBase + bs_h;

    float2 pa0, pa1, pw;
    float4 pb00, pb01, pb10, pb11;

    #define V12S_PRE(jt) do {                                          \
        pa0  = *(const float2*)(v12_hq0 + hqOff + (jt));               \
        pa1  = *(const float2*)(v12_hq1 + hqOff + (jt));               \
        pb00 = *(const float4*)(v12_hs0 + hsOff + (jt));               \
        pb01 = *(const float4*)(v12_hs0 + hsOff + (jt) + 4);           \
        pb10 = *(const float4*)(v12_hs1 + hsOff + (jt));               \
        pb11 = *(const float4*)(v12_hs1 + hsOff + (jt) + 4);           \
        if (tid < 8) pw = *(const float2*)(W2 + jcBase + (jt) + tid * 2); \
    } while (0)

    #define V12S_STAGE(buf) do {                                                            \
        Aq2[(buf)*272 + aq_jp*34 + aq_q] = make_float2(pa0.x + pa1.x, pa0.y + pa1.y);       \
        Bs2[(buf)*1040 + (bs_jp+0)*130 + bs_s] = make_float2(pb00.x + pb10.x, pb00.y + pb10.y); \
        Bs2[(buf)*1040 + (bs_jp+1)*130 + bs_s] = make_float2(pb00.z + pb10.z, pb00.w + pb10.w); \
        Bs2[(buf)*1040 + (bs_jp+2)*130 + bs_s] = make_float2(pb01.x + pb11.x, pb01.y + pb11.y); \
        Bs2[(buf)*1040 + (bs_jp+3)*130 + bs_s] = make_float2(pb01.z + pb11.z, pb01.w + pb11.w); \
        if (tid < 8) ws2[(buf)*8 + tid] = pw;                                               \
    } while (0)

    ull acc2[2][8] = {};

    V12S_PRE(0);
    V12S_STAGE(0);
    V12S_PRE(16);

    for (int it = 0; it < 12; it++) {
        const int buf = it & 1;
        __syncthreads();
        if (it < 11) {
            V12S_STAGE(buf ^ 1);
            if (it < 10) V12S_PRE((it + 2) * 16);
        }

        #pragma unroll
        for (int jp = 0; jp < 8; jp++) {
            const ull w2v = *(const ull*)&ws2[buf*8 + jp];
            const ull a0  = *(const ull*)&Aq2[buf*272 + jp*34 + ty*2];
            const ull a1  = *(const ull*)&Aq2[buf*272 + jp*34 + ty*2 + 1];
            #pragma unroll
            for (int l = 0; l < 8; l++) {
                const ull bv = *(const ull*)&Bs2[buf*1040 + jp*130 + tx + l*16];
                ull t0; V12_ADD2(t0, a0, bv);
                t0 = v12_relu2(t0);
                V12_FMA2(acc2[0][l], t0, w2v);
                ull t1; V12_ADD2(t1, a1, bv);
                t1 = v12_relu2(t1);
                V12_FMA2(acc2[1][l], t1, w2v);
            }
        }
    }

    // ---- phase 2: overlay smem, write chunk scores, bin by class ----
    __syncthreads();   // all staging reads done before overlay writes

    #pragma unroll
    for (int i = 0; i < 2; i++)
        #pragma unroll
        for (int l = 0; l < 8; l++) {
            unsigned lo, hi;
            asm("mov.b64 {%0,%1}, %2;" : "=r"(lo), "=r"(hi) : "l"(acc2[i][l]));
            scr[(ty*2 + i) * 129 + tx + l*16] =
                (double)(__uint_as_float(lo) + __uint_as_float(hi));
        }
    if (tid < 128) lab2[tid] = labels[sBase + tid];
    __syncthreads();

    if (tid <= 64) {   // segment table: seg[c] = lower_bound(lab2, c), seg[64] = lb(64)=128
        const int c = tid;
        int lo = 0, hi = 128;
        while (lo < hi) { int m = (lo + hi) >> 1; if (lab2[m] < c) lo = m + 1; else hi = m; }
        seg[tid] = lo;
    }
    __syncthreads();

    const int cb = blockIdx.z * 4 + blockIdx.x;      // chunk-block id, jc-major
    double* outp = v12_part2 + ((size_t)cb * Q_N + qBase) * C_N;
    #pragma unroll
    for (int k = 0; k < 8; k++) {
        const int p  = tid + k * 256;                // p = qlocal*64 + c
        const int qq = p >> 6;
        const int cc = p & 63;
        double ssum = 0.0;
        const int s0 = seg[cc], s1 = seg[cc + 1];
        for (int s = s0; s < s1; s++) ssum += scr[qq * 129 + s];
        outp[p] = ssum;
    }
}

// ---------------------------------------------------------------------------
// Light aggregate: per-query block sums 32 class-binned partials (fixed order),
// counts via binary search on sorted labels, softmax/argmax/loss, ticket final.
// grid = 128 blocks, 128 threads. All fp64, deterministic.
// ---------------------------------------------------------------------------
__global__ void v12_agg(const int* __restrict__ labels,
                        const int* __restrict__ targets,
                        const float* __restrict__ b2,
                        float* __restrict__ out, int out_size)
{
    __shared__ int    lab[S_N];
    __shared__ double aggv[C_N];
    __shared__ double redv[C_N];
    __shared__ int    redi[C_N];
    __shared__ double rede[C_N];
    __shared__ int    isLast;
    __shared__ double lred[Q_N];

    const int q   = blockIdx.x;
    const int tid = threadIdx.x;

    for (int i = tid; i < S_N; i += 128) lab[i] = labels[i];
    __syncthreads();

    if (tid < C_N) {
        const double* P = v12_part2 + (size_t)q * C_N + tid;
        double s0 = 0.0, s1 = 0.0, s2 = 0.0, s3 = 0.0;
        #pragma unroll
        for (int cb = 0; cb < NCB; cb += 4) {
            s0 += P[(size_t)(cb + 0) * (Q_N * C_N)];
            s1 += P[(size_t)(cb + 1) * (Q_N * C_N)];
            s2 += P[(size_t)(cb + 2) * (Q_N * C_N)];
            s3 += P[(size_t)(cb + 3) * (Q_N * C_N)];
        }
        const double tot = (s0 + s1) + (s2 + s3);

        const int c = tid;
        int lo = 0, hi = S_N;
        while (lo < hi) { int m = (lo + hi) >> 1; if (lab[m] < c) lo = m + 1; else hi = m; }
        int lo2 = lo, hi2 = S_N;
        while (lo2 < hi2) { int m = (lo2 + hi2) >> 1; if (lab[m] < c + 1) lo2 = m + 1; else hi2 = m; }
        const int cnt = lo2 - lo;

        aggv[tid] = tot / (double)(cnt > 1 ? cnt : 1) + (double)b2[0];
        redv[tid] = aggv[tid];
        redi[tid] = tid;
    }
    __syncthreads();

    #pragma unroll
    for (int off = C_N / 2; off > 0; off >>= 1) {
        if (tid < off) {
            if (redv[tid + off] > redv[tid] ||
                (redv[tid + off] == redv[tid] && redi[tid + off] < redi[tid])) {
                redv[tid] = redv[tid + off];
                redi[tid] = redi[tid + off];
            }
        }
        __syncthreads();
    }
    const double mx = redv[0];
    const int    am = redi[0];

    if (tid < C_N) rede[tid] = exp(aggv[tid] - mx);
    __syncthreads();
    #pragma unroll
    for (int off = C_N / 2; off > 0; off >>= 1) {
        if (tid < off) rede[tid] += rede[tid + off];
        __syncthreads();
    }

    if (tid == 0) {
        const int tgt = targets[q];
        const double logp = aggv[tgt] - mx - log(rede[0]);
        v12_loss[q] = -logp;
        if (1 + q < out_size) out[1 + q] = (am == tgt) ? 1.0f : 0.0f;
        __threadfence();
        unsigned tk = atomicAdd(&v12_ticket, 1u);
        isLast = (tk == (unsigned)(Q_N - 1));
    }
    __syncthreads();

    if (isLast) {
        __threadfence();
        lred[tid] = v12_loss[tid];
        __syncthreads();
        #pragma unroll
        for (int off = Q_N / 2; off > 0; off >>= 1) {
            if (tid < off) lred[tid] += lred[tid + off];
            __syncthreads();
        }
        if (tid == 0) {
            if (out_size > 0) out[0] = (float)(lred[0] / (double)Q_N);
            v12_ticket = 0;
        }
    }
}

// ---------------------------------------------------------------------------
extern "C" void kernel_launch(void* const* d_in, const int* in_sizes, int n_in,
                              void* d_out, int out_size)
{
    const float* query   = (const float*)d_in[0];
    const float* support = (const float*)d_in[1];
    const float* W1      = (const float*)d_in[2];
    const float* b1      = (const float*)d_in[3];
    const float* W2      = (const float*)d_in[4];
    const float* b2      = (const float*)d_in[5];
    const int*   labels  = (const int*)  d_in[6];
    const int*   targets = (const int*)  d_in[7];
    (void)in_sizes; (void)n_in;

    float* out = (float*)d_out;

    cudaFuncSetAttribute(v12_gemm, cudaFuncAttributeMaxDynamicSharedMemorySize, V12_SMEM);

    v12_gemm  <<<dim3(12, 10, 2), 256, V12_SMEM>>>(query, support, W1, b1);
    v12_scores<<<dim3(4, 4, JCHUNKS), 256, V12S_DYN>>>(W2, labels);
    v12_agg   <<<Q_N, 128>>>(labels, targets, b2, out, out_size);
}